// round 11
// baseline (speedup 1.0000x reference)
#include <cuda_runtime.h>
#include <cuda_fp16.h>
#include <cstdint>

#define NN 100000
#define EE 1600000
#define HD 128
#define FIN 64
#define NLAYER 3
#define SCAN_BLK 1024
#define NSCAN ((NN + SCAN_BLK - 1) / SCAN_BLK)   // 98
#define NWELEM (FIN * HD + NLAYER * HD * HD)     // 57344
#define BST 40   // B smem stride (halves)
#define AST 40   // A smem stride (halves)
#define XQUAD (NN * FIN / 4)                     // 1.6M float4 elements

// ---------------- device scratch ----------------
__device__ float  g_dinv[NN];
__device__ int    g_cnt[NN + 1];           // [NN] = scan done-counter
__device__ int    g_rowptr[NN + 1];
__device__ int    g_blocksum[NSCAN + 1];
__device__ int    g_rank[EE];
__device__ int2   g_csr[EE];               // {src, weight-as-int}
__device__ float  g_t[NN];
__device__ __half g_x16[(size_t)NN * FIN];
__device__ __half g_h16[(size_t)NN * HD];
__device__ __half g_g16[(size_t)NN * HD];
__device__ __half g_WhiT[NWELEM];          // [n][k] fp16 hi
__device__ __half g_WloT[NWELEM];          // [n][k] fp16 lo

// ---------------- prep: weight split + x convert ----------------
__global__ void k_prep(const float* __restrict__ x, const float* __restrict__ W1,
                       const float* __restrict__ W2) {
    int i = blockIdx.x * blockDim.x + threadIdx.x;
    if (i < XQUAD) {
        float4 v = ((const float4*)x)[i];
        __half2 h0 = __floats2half2_rn(v.x, v.y);
        __half2 h1 = __floats2half2_rn(v.z, v.w);
        uint2 o;
        o.x = *reinterpret_cast<uint32_t*>(&h0);
        o.y = *reinterpret_cast<uint32_t*>(&h1);
        ((uint2*)g_x16)[i] = o;
    }
    if (i < NWELEM) {
        float v;
        int oidx;
        if (i < FIN * HD) {
            int k = i / HD, n = i % HD;
            v = W1[i];
            oidx = n * FIN + k;
        } else {
            int j = i - FIN * HD;
            int l = j / (HD * HD), r = j % (HD * HD);
            int k = r / HD, n = r % HD;
            v = W2[j];
            oidx = FIN * HD + l * HD * HD + n * HD + k;
        }
        __half hi = __float2half_rn(v);
        float lof = v - __half2float(hi);
        g_WhiT[oidx] = hi;
        g_WloT[oidx] = __float2half_rn(lof);
    }
}

// ---------------- degree / norm / CSR build ----------------
__global__ void k_hist(const int* __restrict__ dst) {
    int t = blockIdx.x * blockDim.x + threadIdx.x;
    int e = t * 4;
    if (e + 3 < EE) {
        int4 d = *(const int4*)(dst + e);
        int4 r;
        r.x = atomicAdd(&g_cnt[d.x], 1);
        r.y = atomicAdd(&g_cnt[d.y], 1);
        r.z = atomicAdd(&g_cnt[d.z], 1);
        r.w = atomicAdd(&g_cnt[d.w], 1);
        *(int4*)(g_rank + e) = r;
    } else {
        for (int k = e; k < EE; k++) g_rank[k] = atomicAdd(&g_cnt[dst[k]], 1);
    }
}
__global__ void k_scan1() {
    __shared__ int sh[SCAN_BLK];
    __shared__ int s_last;
    int i = blockIdx.x * SCAN_BLK + threadIdx.x;
    int v = (i < NN) ? g_cnt[i] : 0;
    if (i < NN) g_dinv[i] = rsqrtf((float)(v + 1));
    sh[threadIdx.x] = v;
    __syncthreads();
    int acc = v;
#pragma unroll
    for (int off = 1; off < SCAN_BLK; off <<= 1) {
        int t = (threadIdx.x >= off) ? sh[threadIdx.x - off] : 0;
        __syncthreads();
        acc += t;
        sh[threadIdx.x] = acc;
        __syncthreads();
    }
    if (i < NN) g_rowptr[i] = acc - v;
    if (threadIdx.x == SCAN_BLK - 1) g_blocksum[blockIdx.x] = acc;
    __threadfence();
    __syncthreads();
    if (threadIdx.x == 0) {
        int d = atomicAdd(&g_cnt[NN], 1);
        s_last = (d == NSCAN - 1);
    }
    __syncthreads();
    if (s_last) {
        int j = threadIdx.x;
        int bv = (j < NSCAN) ? g_blocksum[j] : 0;
        sh[threadIdx.x] = bv;
        __syncthreads();
        int bacc = bv;
#pragma unroll
        for (int off = 1; off < 128; off <<= 1) {
            int tt = (j >= off && j < 128) ? sh[j - off] : 0;
            __syncthreads();
            if (j < 128) { bacc += tt; sh[j] = bacc; }
            __syncthreads();
        }
        if (j < NSCAN) g_blocksum[j] = bacc - bv;
    }
}
__global__ void k_scan3() {
    int i = blockIdx.x * blockDim.x + threadIdx.x;
    if (i < NN) g_rowptr[i] += g_blocksum[i / SCAN_BLK];
    if (i == 0) g_rowptr[NN] = EE;
}
__global__ void k_scatter(const int* __restrict__ src, const int* __restrict__ dst) {
    int t = blockIdx.x * blockDim.x + threadIdx.x;
    int e = t * 4;
    if (e + 3 < EE) {
        int4 s4 = *(const int4*)(src + e);
        int4 d4 = *(const int4*)(dst + e);
        int4 r4 = *(const int4*)(g_rank + e);
#pragma unroll
        for (int k = 0; k < 4; k++) {
            int s = (&s4.x)[k], d = (&d4.x)[k], r = (&r4.x)[k];
            float w = g_dinv[s] * g_dinv[d];
            g_csr[g_rowptr[d] + r] = make_int2(s, __float_as_int(w));
        }
    } else {
        for (int k = e; k < EE; k++) {
            int s = src[k], d = dst[k], r = g_rank[k];
            float w = g_dinv[s] * g_dinv[d];
            g_csr[g_rowptr[d] + r] = make_int2(s, __float_as_int(w));
        }
    }
}

// ---------------- gather aggregation (warp per node), bias+relu ----------------
template <bool LAST>
__global__ void __launch_bounds__(256)
k_agg128(const __half* __restrict__ in, const float* __restrict__ bias,
         __half* __restrict__ out, const float* __restrict__ W3,
         float* __restrict__ tout) {
    int node = blockIdx.x * 8 + (threadIdx.x >> 5);
    int lane = threadIdx.x & 31;
    if (node >= NN) return;
    const uint2* in2 = (const uint2*)in;
    float di = g_dinv[node];
    float w = di * di;
    uint2 sv = in2[(size_t)node * 32 + lane];
    float2 f0 = __half22float2(*reinterpret_cast<__half2*>(&sv.x));
    float2 f1 = __half22float2(*reinterpret_cast<__half2*>(&sv.y));
    float a0 = f0.x * w, a1 = f0.y * w, a2 = f1.x * w, a3 = f1.y * w;

    int j = g_rowptr[node], end = g_rowptr[node + 1];
    for (; j + 1 < end; j += 2) {
        int2 e0 = g_csr[j], e1 = g_csr[j + 1];
        float w0 = __int_as_float(e0.y), w1 = __int_as_float(e1.y);
        uint2 v0 = in2[(size_t)e0.x * 32 + lane];
        uint2 v1 = in2[(size_t)e1.x * 32 + lane];
        float2 u0 = __half22float2(*reinterpret_cast<__half2*>(&v0.x));
        float2 u1 = __half22float2(*reinterpret_cast<__half2*>(&v0.y));
        float2 u2 = __half22float2(*reinterpret_cast<__half2*>(&v1.x));
        float2 u3 = __half22float2(*reinterpret_cast<__half2*>(&v1.y));
        a0 += u0.x * w0 + u2.x * w1;
        a1 += u0.y * w0 + u2.y * w1;
        a2 += u1.x * w0 + u3.x * w1;
        a3 += u1.y * w0 + u3.y * w1;
    }
    if (j < end) {
        int2 e0 = g_csr[j];
        float w0 = __int_as_float(e0.y);
        uint2 v0 = in2[(size_t)e0.x * 32 + lane];
        float2 u0 = __half22float2(*reinterpret_cast<__half2*>(&v0.x));
        float2 u1 = __half22float2(*reinterpret_cast<__half2*>(&v0.y));
        a0 += u0.x * w0; a1 += u0.y * w0; a2 += u1.x * w0; a3 += u1.y * w0;
    }
    float4 b = *(const float4*)(bias + lane * 4);
    a0 = fmaxf(a0 + b.x, 0.f); a1 = fmaxf(a1 + b.y, 0.f);
    a2 = fmaxf(a2 + b.z, 0.f); a3 = fmaxf(a3 + b.w, 0.f);
    if (LAST) {
        float4 w3 = *(const float4*)(W3 + lane * 4);
        float s = a0 * w3.x + a1 * w3.y + a2 * w3.z + a3 * w3.w;
#pragma unroll
        for (int off = 16; off > 0; off >>= 1) s += __shfl_xor_sync(0xffffffffu, s, off);
        if (lane == 0) tout[node] = s;
    } else {
        __half2 o0 = __floats2half2_rn(a0, a1);
        __half2 o1 = __floats2half2_rn(a2, a3);
        uint2 ov;
        ov.x = *reinterpret_cast<uint32_t*>(&o0);
        ov.y = *reinterpret_cast<uint32_t*>(&o1);
        ((uint2*)out)[(size_t)node * 32 + lane] = ov;
    }
}

// ---------------- fp16 tensor-core GEMM (mma.sync): C[N,128] = A[N,K]@(Whi+Wlo) ----------------
#define MMA_F16(d, a0, a1, a2, a3, b0, b1)                                  \
    asm volatile("mma.sync.aligned.m16n8k16.row.col.f32.f16.f16.f32 "       \
                 "{%0,%1,%2,%3}, {%4,%5,%6,%7}, {%8,%9}, {%0,%1,%2,%3};"    \
                 : "+f"(d[0]), "+f"(d[1]), "+f"(d[2]), "+f"(d[3])           \
                 : "r"(a0), "r"(a1), "r"(a2), "r"(a3), "r"(b0), "r"(b1))

template <int K>
__global__ void __launch_bounds__(256, 2)
k_gemm16(const __half* __restrict__ A, const __half* __restrict__ BhiT,
         const __half* __restrict__ BloT, __half* __restrict__ Cout) {
    __shared__ __half As[128 * AST];
    __shared__ __half Bhi[128 * BST];
    __shared__ __half Blo[128 * BST];

    int tid = threadIdx.x;
    int wid = tid >> 5, lane = tid & 31;
    int wr = wid >> 1, wc = wid & 1;
    int row0 = blockIdx.x * 128;
    int mrow = wr * 32;
    int ncol = wc * 64;
    int lq = lane >> 2;
    int lr = lane & 3;

    float acc[2][8][4];
#pragma unroll
    for (int ma = 0; ma < 2; ma++)
#pragma unroll
        for (int na = 0; na < 8; na++)
#pragma unroll
            for (int r = 0; r < 4; r++) acc[ma][na][r] = 0.0f;

    for (int k0 = 0; k0 < K; k0 += 32) {
#pragma unroll
        for (int i = 0; i < 2; i++) {
            int li = tid + i * 256;
            int r = li >> 2;
            int c = (li & 3) * 8;
            uint4 v = make_uint4(0, 0, 0, 0);
            int gr = row0 + r;
            if (gr < NN) v = *(const uint4*)(A + (size_t)gr * K + k0 + c);
            *(uint4*)&As[r * AST + c] = v;
        }
#pragma unroll
        for (int i = 0; i < 2; i++) {
            int li = tid + i * 256;
            int n = li >> 2;
            int c = (li & 3) * 8;
            *(uint4*)&Bhi[n * BST + c] = *(const uint4*)(BhiT + (size_t)n * K + k0 + c);
            *(uint4*)&Blo[n * BST + c] = *(const uint4*)(BloT + (size_t)n * K + k0 + c);
        }
        __syncthreads();
#pragma unroll
        for (int ks = 0; ks < 2; ks++) {
            int kk = ks * 16;
            uint32_t a[2][4];
#pragma unroll
            for (int ma = 0; ma < 2; ma++) {
                int rb = mrow + ma * 16;
                a[ma][0] = *(const uint32_t*)&As[(rb + lq) * AST + kk + 2 * lr];
                a[ma][1] = *(const uint32_t*)&As[(rb + lq + 8) * AST + kk + 2 * lr];
                a[ma][2] = *(const uint32_t*)&As[(rb + lq) * AST + kk + 2 * lr + 8];
                a[ma][3] = *(const uint32_t*)&As[(rb + lq + 8) * AST + kk + 2 * lr + 8];
            }
#pragma unroll
            for (int na = 0; na < 8; na++) {
                int n = ncol + na * 8 + lq;
                uint32_t bh0 = *(const uint32_t*)&Bhi[n * BST + kk + 2 * lr];
                uint32_t bh1 = *(const uint32_t*)&Bhi[n * BST + kk + 2 * lr + 8];
                uint32_t bl0 = *(const uint32_t*)&Blo[n * BST + kk + 2 * lr];
                uint32_t bl1 = *(const uint32_t*)&Blo[n * BST + kk + 2 * lr + 8];
#pragma unroll
                for (int ma = 0; ma < 2; ma++) {
                    MMA_F16(acc[ma][na], a[ma][0], a[ma][1], a[ma][2], a[ma][3], bh0, bh1);
                    MMA_F16(acc[ma][na], a[ma][0], a[ma][1], a[ma][2], a[ma][3], bl0, bl1);
                }
            }
        }
        __syncthreads();
    }
#pragma unroll
    for (int ma = 0; ma < 2; ma++) {
        int r0 = row0 + mrow + ma * 16 + lq;
#pragma unroll
        for (int na = 0; na < 8; na++) {
            int col = ncol + na * 8 + 2 * lr;
            __half2 v0 = __floats2half2_rn(acc[ma][na][0], acc[ma][na][1]);
            __half2 v1 = __floats2half2_rn(acc[ma][na][2], acc[ma][na][3]);
            if (r0 < NN)     *(__half2*)(Cout + (size_t)r0 * 128 + col) = v0;
            if (r0 + 8 < NN) *(__half2*)(Cout + (size_t)(r0 + 8) * 128 + col) = v1;
        }
    }
}

// ---------------- output: F=1 gather ----------------
__global__ void k_final(const float* __restrict__ t, const float* __restrict__ b3,
                        float* __restrict__ out) {
    int i = blockIdx.x * blockDim.x + threadIdx.x;
    if (i >= NN) return;
    float di = g_dinv[i];
    float s = t[i] * di * di + b3[0];
    int j = g_rowptr[i], end = g_rowptr[i + 1];
    for (; j < end; j++) {
        int2 e = g_csr[j];
        s += t[e.x] * __int_as_float(e.y);
    }
    out[i] = s;
}

// ---------------- launch ----------------
extern "C" void kernel_launch(void* const* d_in, const int* in_sizes, int n_in,
                              void* d_out, int out_size) {
    const float* x  = (const float*)d_in[0];
    const int* ei   = (const int*)d_in[1];
    const float* W1 = (const float*)d_in[2];
    const float* b1 = (const float*)d_in[3];
    const float* W2 = (const float*)d_in[4];
    const float* b2 = (const float*)d_in[5];
    const float* W3 = (const float*)d_in[6];
    const float* b3 = (const float*)d_in[7];
    float* out = (float*)d_out;

    const int* src = ei;
    const int* dst = ei + EE;

    __half* x16;  cudaGetSymbolAddress((void**)&x16, g_x16);
    __half* h16;  cudaGetSymbolAddress((void**)&h16, g_h16);
    __half* g16;  cudaGetSymbolAddress((void**)&g16, g_g16);
    __half* whiT; cudaGetSymbolAddress((void**)&whiT, g_WhiT);
    __half* wloT; cudaGetSymbolAddress((void**)&wloT, g_WloT);
    float* tbuf;  cudaGetSymbolAddress((void**)&tbuf, g_t);
    int* cntp;    cudaGetSymbolAddress((void**)&cntp, g_cnt);

    static cudaStream_t s2 = nullptr;
    static cudaEvent_t evFork = nullptr, evJoin = nullptr;
    if (!s2) {
        cudaStreamCreateWithFlags(&s2, cudaStreamNonBlocking);
        cudaEventCreateWithFlags(&evFork, cudaEventDisableTiming);
        cudaEventCreateWithFlags(&evJoin, cudaEventDisableTiming);
    }

    // fork: CSR chain on s2; prep + layer-1 GEMM (no CSR dep) on main stream
    cudaEventRecord(evFork, 0);
    cudaStreamWaitEvent(s2, evFork, 0);

    cudaMemsetAsync(cntp, 0, (NN + 1) * sizeof(int), s2);
    k_hist<<<(EE / 4 + 255) / 256, 256, 0, s2>>>(dst);
    k_scan1<<<NSCAN, SCAN_BLK, 0, s2>>>();
    k_scan3<<<(NN + 255) / 256, 256, 0, s2>>>();
    k_scatter<<<(EE / 4 + 255) / 256, 256, 0, s2>>>(src, dst);
    cudaEventRecord(evJoin, s2);

    const int GB = (NN + 127) / 128;

    k_prep<<<(XQUAD + 255) / 256, 256>>>(x, W1, W2);
    // layer 1 GEMM-first: g = x @ W1 (fully overlapped with CSR build)
    k_gemm16<FIN><<<GB, 256>>>(x16, whiT, wloT, g16);

    // join: CSR needed from here on
    cudaStreamWaitEvent(0, evJoin, 0);

    // layer 1 aggregation: h = relu(agg(g) + b1)
    k_agg128<false><<<(NN + 7) / 8, 256>>>(g16, b1, h16, nullptr, nullptr);

    // hidden layers: GEMM then agg (bias+relu); last agg fuses the 128->1 matvec
    for (int l = 0; l < NLAYER; l++) {
        const __half* bh = whiT + FIN * HD + (size_t)l * HD * HD;
        const __half* bl = wloT + FIN * HD + (size_t)l * HD * HD;
        k_gemm16<HD><<<GB, 256>>>(h16, bh, bl, g16);
        if (l < NLAYER - 1)
            k_agg128<false><<<(NN + 7) / 8, 256>>>(g16, b2 + (size_t)l * HD,
                                                   h16, nullptr, nullptr);
        else
            k_agg128<true><<<(NN + 7) / 8, 256>>>(g16, b2 + (size_t)l * HD,
                                                  nullptr, W3, tbuf);
    }

    // output: F=1 gather + b3
    k_final<<<(NN + 255) / 256, 256>>>(tbuf, b3, out);
}

// round 12
// speedup vs baseline: 1.0516x; 1.0516x over previous
#include <cuda_runtime.h>
#include <cuda_fp16.h>
#include <cstdint>

#define NN 100000
#define EE 1600000
#define HD 128
#define FIN 64
#define NLAYER 3
#define SCAN_BLK 1024
#define NSCAN ((NN + SCAN_BLK - 1) / SCAN_BLK)   // 98
#define NWELEM (FIN * HD + NLAYER * HD * HD)     // 57344
#define ASTRIDE 40                               // A-stage stride (halves)
#define XQUAD (NN * FIN / 4)                     // 1.6M float4 elements

// ---------------- device scratch ----------------
__device__ float  g_dinv[NN];
__device__ int    g_cnt[NN + 1];           // [NN] = scan done-counter
__device__ int    g_rowptr[NN + 1];
__device__ int    g_blocksum[NSCAN + 1];
__device__ int    g_rank[EE];
__device__ int2   g_csr[EE];               // {src, weight-as-int}
__device__ float  g_t[NN];
__device__ __half g_x16[(size_t)NN * FIN];
__device__ __half g_a64[(size_t)NN * FIN];
__device__ __half g_h16[(size_t)NN * HD];
__device__ __half g_g16[(size_t)NN * HD];
__device__ __half g_WhiT[NWELEM];          // [n][k] fp16 hi
__device__ __half g_WloT[NWELEM];          // [n][k] fp16 lo

__device__ __forceinline__ uint32_t smem_u32(const void* p) {
    uint32_t a;
    asm("{ .reg .u64 t; cvta.to.shared.u64 t, %1; cvt.u32.u64 %0, t; }" : "=r"(a) : "l"(p));
    return a;
}

// ---------------- prep: weight split + x convert ----------------
__global__ void k_prep(const float* __restrict__ x, const float* __restrict__ W1,
                       const float* __restrict__ W2) {
    int i = blockIdx.x * blockDim.x + threadIdx.x;
    if (i < XQUAD) {
        float4 v = ((const float4*)x)[i];
        __half2 h0 = __floats2half2_rn(v.x, v.y);
        __half2 h1 = __floats2half2_rn(v.z, v.w);
        uint2 o;
        o.x = *reinterpret_cast<uint32_t*>(&h0);
        o.y = *reinterpret_cast<uint32_t*>(&h1);
        ((uint2*)g_x16)[i] = o;
    }
    if (i < NWELEM) {
        float v;
        int oidx;
        if (i < FIN * HD) {
            int k = i / HD, n = i % HD;
            v = W1[i];
            oidx = n * FIN + k;
        } else {
            int j = i - FIN * HD;
            int l = j / (HD * HD), r = j % (HD * HD);
            int k = r / HD, n = r % HD;
            v = W2[j];
            oidx = FIN * HD + l * HD * HD + n * HD + k;
        }
        __half hi = __float2half_rn(v);
        float lof = v - __half2float(hi);
        g_WhiT[oidx] = hi;
        g_WloT[oidx] = __float2half_rn(lof);
    }
}

// ---------------- degree / norm / CSR build ----------------
__global__ void k_hist(const int* __restrict__ dst) {
    int t = blockIdx.x * blockDim.x + threadIdx.x;
    int e = t * 4;
    if (e + 3 < EE) {
        int4 d = *(const int4*)(dst + e);
        int4 r;
        r.x = atomicAdd(&g_cnt[d.x], 1);
        r.y = atomicAdd(&g_cnt[d.y], 1);
        r.z = atomicAdd(&g_cnt[d.z], 1);
        r.w = atomicAdd(&g_cnt[d.w], 1);
        *(int4*)(g_rank + e) = r;
    } else {
        for (int k = e; k < EE; k++) g_rank[k] = atomicAdd(&g_cnt[dst[k]], 1);
    }
}
__global__ void k_scan1() {
    __shared__ int sh[SCAN_BLK];
    __shared__ int s_last;
    int i = blockIdx.x * SCAN_BLK + threadIdx.x;
    int v = (i < NN) ? g_cnt[i] : 0;
    if (i < NN) g_dinv[i] = rsqrtf((float)(v + 1));
    sh[threadIdx.x] = v;
    __syncthreads();
    int acc = v;
#pragma unroll
    for (int off = 1; off < SCAN_BLK; off <<= 1) {
        int t = (threadIdx.x >= off) ? sh[threadIdx.x - off] : 0;
        __syncthreads();
        acc += t;
        sh[threadIdx.x] = acc;
        __syncthreads();
    }
    if (i < NN) g_rowptr[i] = acc - v;
    if (threadIdx.x == SCAN_BLK - 1) g_blocksum[blockIdx.x] = acc;
    __threadfence();
    __syncthreads();
    if (threadIdx.x == 0) {
        int d = atomicAdd(&g_cnt[NN], 1);
        s_last = (d == NSCAN - 1);
    }
    __syncthreads();
    if (s_last) {
        int j = threadIdx.x;
        int bv = (j < NSCAN) ? g_blocksum[j] : 0;
        sh[threadIdx.x] = bv;
        __syncthreads();
        int bacc = bv;
#pragma unroll
        for (int off = 1; off < 128; off <<= 1) {
            int tt = (j >= off && j < 128) ? sh[j - off] : 0;
            __syncthreads();
            if (j < 128) { bacc += tt; sh[j] = bacc; }
            __syncthreads();
        }
        if (j < NSCAN) g_blocksum[j] = bacc - bv;
    }
}
__global__ void k_scan3() {
    int i = blockIdx.x * blockDim.x + threadIdx.x;
    if (i < NN) g_rowptr[i] += g_blocksum[i / SCAN_BLK];
    if (i == 0) g_rowptr[NN] = EE;
}
__global__ void k_scatter(const int* __restrict__ src, const int* __restrict__ dst) {
    int t = blockIdx.x * blockDim.x + threadIdx.x;
    int e = t * 4;
    if (e + 3 < EE) {
        int4 s4 = *(const int4*)(src + e);
        int4 d4 = *(const int4*)(dst + e);
        int4 r4 = *(const int4*)(g_rank + e);
#pragma unroll
        for (int k = 0; k < 4; k++) {
            int s = (&s4.x)[k], d = (&d4.x)[k], r = (&r4.x)[k];
            float w = g_dinv[s] * g_dinv[d];
            g_csr[g_rowptr[d] + r] = make_int2(s, __float_as_int(w));
        }
    } else {
        for (int k = e; k < EE; k++) {
            int s = src[k], d = dst[k], r = g_rank[k];
            float w = g_dinv[s] * g_dinv[d];
            g_csr[g_rowptr[d] + r] = make_int2(s, __float_as_int(w));
        }
    }
}

// ---------------- gather aggregations (warp per node) ----------------
__global__ void __launch_bounds__(256)
k_agg64(const __half* __restrict__ in, __half* __restrict__ out) {
    int node = blockIdx.x * 8 + (threadIdx.x >> 5);
    int lane = threadIdx.x & 31;
    if (node >= NN) return;
    const uint32_t* in1 = (const uint32_t*)in;
    float di = g_dinv[node];
    float w = di * di;
    uint32_t sv = in1[(size_t)node * 32 + lane];
    float2 f = __half22float2(*reinterpret_cast<__half2*>(&sv));
    float a0 = f.x * w, a1 = f.y * w;
    int j = g_rowptr[node], end = g_rowptr[node + 1];
    for (; j + 1 < end; j += 2) {
        int2 e0 = g_csr[j], e1 = g_csr[j + 1];
        float w0 = __int_as_float(e0.y), w1 = __int_as_float(e1.y);
        uint32_t v0 = in1[(size_t)e0.x * 32 + lane];
        uint32_t v1 = in1[(size_t)e1.x * 32 + lane];
        float2 u0 = __half22float2(*reinterpret_cast<__half2*>(&v0));
        float2 u1 = __half22float2(*reinterpret_cast<__half2*>(&v1));
        a0 += u0.x * w0 + u1.x * w1;
        a1 += u0.y * w0 + u1.y * w1;
    }
    if (j < end) {
        int2 e0 = g_csr[j];
        float w0 = __int_as_float(e0.y);
        uint32_t v0 = in1[(size_t)e0.x * 32 + lane];
        float2 u0 = __half22float2(*reinterpret_cast<__half2*>(&v0));
        a0 += u0.x * w0; a1 += u0.y * w0;
    }
    __half2 o = __floats2half2_rn(a0, a1);
    ((uint32_t*)out)[(size_t)node * 32 + lane] = *reinterpret_cast<uint32_t*>(&o);
}

template <bool LAST>
__global__ void __launch_bounds__(256)
k_agg128(const __half* __restrict__ in, const float* __restrict__ bias,
         __half* __restrict__ out, const float* __restrict__ W3,
         float* __restrict__ tout) {
    int node = blockIdx.x * 8 + (threadIdx.x >> 5);
    int lane = threadIdx.x & 31;
    if (node >= NN) return;
    const uint2* in2 = (const uint2*)in;
    float di = g_dinv[node];
    float w = di * di;
    uint2 sv = in2[(size_t)node * 32 + lane];
    float2 f0 = __half22float2(*reinterpret_cast<__half2*>(&sv.x));
    float2 f1 = __half22float2(*reinterpret_cast<__half2*>(&sv.y));
    float a0 = f0.x * w, a1 = f0.y * w, a2 = f1.x * w, a3 = f1.y * w;

    int j = g_rowptr[node], end = g_rowptr[node + 1];
    for (; j + 1 < end; j += 2) {
        int2 e0 = g_csr[j], e1 = g_csr[j + 1];
        float w0 = __int_as_float(e0.y), w1 = __int_as_float(e1.y);
        uint2 v0 = in2[(size_t)e0.x * 32 + lane];
        uint2 v1 = in2[(size_t)e1.x * 32 + lane];
        float2 u0 = __half22float2(*reinterpret_cast<__half2*>(&v0.x));
        float2 u1 = __half22float2(*reinterpret_cast<__half2*>(&v0.y));
        float2 u2 = __half22float2(*reinterpret_cast<__half2*>(&v1.x));
        float2 u3 = __half22float2(*reinterpret_cast<__half2*>(&v1.y));
        a0 += u0.x * w0 + u2.x * w1;
        a1 += u0.y * w0 + u2.y * w1;
        a2 += u1.x * w0 + u3.x * w1;
        a3 += u1.y * w0 + u3.y * w1;
    }
    if (j < end) {
        int2 e0 = g_csr[j];
        float w0 = __int_as_float(e0.y);
        uint2 v0 = in2[(size_t)e0.x * 32 + lane];
        float2 u0 = __half22float2(*reinterpret_cast<__half2*>(&v0.x));
        float2 u1 = __half22float2(*reinterpret_cast<__half2*>(&v0.y));
        a0 += u0.x * w0; a1 += u0.y * w0; a2 += u1.x * w0; a3 += u1.y * w0;
    }
    float4 b = *(const float4*)(bias + lane * 4);
    a0 = fmaxf(a0 + b.x, 0.f); a1 = fmaxf(a1 + b.y, 0.f);
    a2 = fmaxf(a2 + b.z, 0.f); a3 = fmaxf(a3 + b.w, 0.f);
    if (LAST) {
        float4 w3 = *(const float4*)(W3 + lane * 4);
        float s = a0 * w3.x + a1 * w3.y + a2 * w3.z + a3 * w3.w;
#pragma unroll
        for (int off = 16; off > 0; off >>= 1) s += __shfl_xor_sync(0xffffffffu, s, off);
        if (lane == 0) tout[node] = s;
    } else {
        __half2 o0 = __floats2half2_rn(a0, a1);
        __half2 o1 = __floats2half2_rn(a2, a3);
        uint2 ov;
        ov.x = *reinterpret_cast<uint32_t*>(&o0);
        ov.y = *reinterpret_cast<uint32_t*>(&o1);
        ((uint2*)out)[(size_t)node * 32 + lane] = ov;
    }
}

// ---------------- pipelined fp16 GEMM: C[N,128] = A[N,K]@(Whi+Wlo) (+bias,relu) ----------------
// B (hi+lo) fully resident in smem; A double-buffered via cp.async.
#define MMA_F16(d, a0, a1, a2, a3, b0, b1)                                  \
    asm volatile("mma.sync.aligned.m16n8k16.row.col.f32.f16.f16.f32 "       \
                 "{%0,%1,%2,%3}, {%4,%5,%6,%7}, {%8,%9}, {%0,%1,%2,%3};"    \
                 : "+f"(d[0]), "+f"(d[1]), "+f"(d[2]), "+f"(d[3])           \
                 : "r"(a0), "r"(a1), "r"(a2), "r"(a3), "r"(b0), "r"(b1))

template <int K, bool BIASRELU>
__global__ void __launch_bounds__(256, 2)
k_gemm16(const __half* __restrict__ A, const __half* __restrict__ BhiT,
         const __half* __restrict__ BloT, const float* __restrict__ bias,
         __half* __restrict__ Cout) {
    constexpr int BS = K + 8;                 // B smem stride (halves)
    constexpr int NSTAGE = K / 32;            // k-tiles of 32 halves
    constexpr int STAGE_H = 128 * ASTRIDE;    // halves per A stage
    extern __shared__ __half smbuf[];
    __half* Bh  = smbuf;                      // 128*BS
    __half* Bl  = Bh + 128 * BS;
    __half* Asm = Bl + 128 * BS;              // 2 stages x 128*ASTRIDE
    uint32_t sA0 = smem_u32(Asm);

    int tid = threadIdx.x;
    int wid = tid >> 5, lane = tid & 31;
    int wr = wid >> 1, wc = wid & 1;
    int row0 = blockIdx.x * 128;
    int mrow = wr * 32;
    int ncol = wc * 64;
    int lq = lane >> 2;
    int lr = lane & 3;

    // load ALL of B (hi+lo) once
    constexpr int BCH = K / 8;                // 16B chunks per B row
    for (int idx = tid; idx < 128 * BCH; idx += 256) {
        int n = idx / BCH, c = (idx % BCH) * 8;
        *(uint4*)&Bh[n * BS + c] = *(const uint4*)(BhiT + (size_t)n * K + c);
        *(uint4*)&Bl[n * BS + c] = *(const uint4*)(BloT + (size_t)n * K + c);
    }

    // async A-stage loader: 32 halves per row into stage buffer
    auto loadA = [&](int stage, int k0) {
#pragma unroll
        for (int i = 0; i < 2; i++) {
            int li = tid + i * 256;
            int r = li >> 2;
            int c = (li & 3) * 8;
            int gr = row0 + r;
            const void* src = (gr < NN) ? (const void*)(A + (size_t)gr * K + k0 + c)
                                        : (const void*)A;
            int sz = (gr < NN) ? 16 : 0;
            uint32_t d = sA0 + (stage * STAGE_H + r * ASTRIDE + c) * 2;
            asm volatile("cp.async.ca.shared.global [%0], [%1], 16, %2;"
                         :: "r"(d), "l"(src), "r"(sz));
        }
        asm volatile("cp.async.commit_group;" ::: "memory");
    };

    float acc[2][8][4];
#pragma unroll
    for (int ma = 0; ma < 2; ma++)
#pragma unroll
        for (int na = 0; na < 8; na++)
#pragma unroll
            for (int r = 0; r < 4; r++) acc[ma][na][r] = 0.0f;

    loadA(0, 0);

#pragma unroll
    for (int st = 0; st < NSTAGE; st++) {
        if (st + 1 < NSTAGE) loadA((st + 1) & 1, (st + 1) * 32);
        if (st + 1 < NSTAGE)
            asm volatile("cp.async.wait_group 1;" ::: "memory");
        else
            asm volatile("cp.async.wait_group 0;" ::: "memory");
        __syncthreads();

        const __half* Ast = Asm + (st & 1) * STAGE_H;
        int gk0 = st * 32;
#pragma unroll
        for (int ks = 0; ks < 2; ks++) {
            int kk = ks * 16;          // local A col
            int gk = gk0 + kk;         // global B col
            uint32_t a[2][4];
#pragma unroll
            for (int ma = 0; ma < 2; ma++) {
                int rb = mrow + ma * 16;
                a[ma][0] = *(const uint32_t*)&Ast[(rb + lq) * ASTRIDE + kk + 2 * lr];
                a[ma][1] = *(const uint32_t*)&Ast[(rb + lq + 8) * ASTRIDE + kk + 2 * lr];
                a[ma][2] = *(const uint32_t*)&Ast[(rb + lq) * ASTRIDE + kk + 2 * lr + 8];
                a[ma][3] = *(const uint32_t*)&Ast[(rb + lq + 8) * ASTRIDE + kk + 2 * lr + 8];
            }
#pragma unroll
            for (int na = 0; na < 8; na++) {
                int n = ncol + na * 8 + lq;
                uint32_t bh0 = *(const uint32_t*)&Bh[n * BS + gk + 2 * lr];
                uint32_t bh1 = *(const uint32_t*)&Bh[n * BS + gk + 2 * lr + 8];
                uint32_t bl0 = *(const uint32_t*)&Bl[n * BS + gk + 2 * lr];
                uint32_t bl1 = *(const uint32_t*)&Bl[n * BS + gk + 2 * lr + 8];
#pragma unroll
                for (int ma = 0; ma < 2; ma++) {
                    MMA_F16(acc[ma][na], a[ma][0], a[ma][1], a[ma][2], a[ma][3], bh0, bh1);
                    MMA_F16(acc[ma][na], a[ma][0], a[ma][1], a[ma][2], a[ma][3], bl0, bl1);
                }
            }
        }
        __syncthreads();
    }

#pragma unroll
    for (int ma = 0; ma < 2; ma++) {
        int r0 = row0 + mrow + ma * 16 + lq;
#pragma unroll
        for (int na = 0; na < 8; na++) {
            int col = ncol + na * 8 + 2 * lr;
            float c0 = acc[ma][na][0], c1 = acc[ma][na][1];
            float c2 = acc[ma][na][2], c3 = acc[ma][na][3];
            if (BIASRELU) {
                float bx = bias[col], by = bias[col + 1];
                c0 = fmaxf(c0 + bx, 0.f); c1 = fmaxf(c1 + by, 0.f);
                c2 = fmaxf(c2 + bx, 0.f); c3 = fmaxf(c3 + by, 0.f);
            }
            if (r0 < NN)     *(__half2*)(Cout + (size_t)r0 * 128 + col) = __floats2half2_rn(c0, c1);
            if (r0 + 8 < NN) *(__half2*)(Cout + (size_t)(r0 + 8) * 128 + col) = __floats2half2_rn(c2, c3);
        }
    }
}

// ---------------- output: F=1 gather ----------------
__global__ void k_final(const float* __restrict__ t, const float* __restrict__ b3,
                        float* __restrict__ out) {
    int i = blockIdx.x * blockDim.x + threadIdx.x;
    if (i >= NN) return;
    float di = g_dinv[i];
    float s = t[i] * di * di + b3[0];
    int j = g_rowptr[i], end = g_rowptr[i + 1];
    for (; j < end; j++) {
        int2 e = g_csr[j];
        s += t[e.x] * __int_as_float(e.y);
    }
    out[i] = s;
}

// ---------------- launch ----------------
extern "C" void kernel_launch(void* const* d_in, const int* in_sizes, int n_in,
                              void* d_out, int out_size) {
    const float* x  = (const float*)d_in[0];
    const int* ei   = (const int*)d_in[1];
    const float* W1 = (const float*)d_in[2];
    const float* b1 = (const float*)d_in[3];
    const float* W2 = (const float*)d_in[4];
    const float* b2 = (const float*)d_in[5];
    const float* W3 = (const float*)d_in[6];
    const float* b3 = (const float*)d_in[7];
    float* out = (float*)d_out;

    const int* src = ei;
    const int* dst = ei + EE;

    __half* x16;  cudaGetSymbolAddress((void**)&x16, g_x16);
    __half* a64;  cudaGetSymbolAddress((void**)&a64, g_a64);
    __half* h16;  cudaGetSymbolAddress((void**)&h16, g_h16);
    __half* g16;  cudaGetSymbolAddress((void**)&g16, g_g16);
    __half* whiT; cudaGetSymbolAddress((void**)&whiT, g_WhiT);
    __half* wloT; cudaGetSymbolAddress((void**)&wloT, g_WloT);
    float* tbuf;  cudaGetSymbolAddress((void**)&tbuf, g_t);
    int* cntp;    cudaGetSymbolAddress((void**)&cntp, g_cnt);

    constexpr int SM64  = (2 * 128 * (FIN + 8) + 2 * 128 * ASTRIDE) * 2;  // 57344
    constexpr int SM128 = (2 * 128 * (HD + 8) + 2 * 128 * ASTRIDE) * 2;   // 90112

    static cudaStream_t s2 = nullptr;
    static cudaEvent_t evFork = nullptr, evJoin = nullptr;
    if (!s2) {
        cudaStreamCreateWithFlags(&s2, cudaStreamNonBlocking);
        cudaEventCreateWithFlags(&evFork, cudaEventDisableTiming);
        cudaEventCreateWithFlags(&evJoin, cudaEventDisableTiming);
        cudaFuncSetAttribute(k_gemm16<FIN, true>,
                             cudaFuncAttributeMaxDynamicSharedMemorySize, SM64);
        cudaFuncSetAttribute(k_gemm16<HD, false>,
                             cudaFuncAttributeMaxDynamicSharedMemorySize, SM128);
    }

    // fork: CSR chain on s2, prep on main stream
    cudaEventRecord(evFork, 0);
    cudaStreamWaitEvent(s2, evFork, 0);

    cudaMemsetAsync(cntp, 0, (NN + 1) * sizeof(int), s2);
    k_hist<<<(EE / 4 + 255) / 256, 256, 0, s2>>>(dst);
    k_scan1<<<NSCAN, SCAN_BLK, 0, s2>>>();
    k_scan3<<<(NN + 255) / 256, 256, 0, s2>>>();
    k_scatter<<<(EE / 4 + 255) / 256, 256, 0, s2>>>(src, dst);
    cudaEventRecord(evJoin, s2);

    k_prep<<<(XQUAD + 255) / 256, 256>>>(x, W1, W2);

    // join before anything that needs the CSR
    cudaStreamWaitEvent(0, evJoin, 0);

    const int GB = (NN + 127) / 128;

    // layer 1: agg-first at F=64 fp16, then pipelined GEMM 64->128 with b1+relu
    k_agg64<<<(NN + 7) / 8, 256>>>(x16, a64);
    k_gemm16<FIN, true><<<GB, 256, SM64>>>(a64, whiT, wloT, b1, h16);

    // hidden layers: GEMM (no bias) then agg128 (bias+relu); last agg fuses matvec
    for (int l = 0; l < NLAYER; l++) {
        const __half* bh = whiT + FIN * HD + (size_t)l * HD * HD;
        const __half* bl = wloT + FIN * HD + (size_t)l * HD * HD;
        k_gemm16<HD, false><<<GB, 256, SM128>>>(h16, bh, bl, nullptr, g16);
        if (l < NLAYER - 1)
            k_agg128<false><<<(NN + 7) / 8, 256>>>(g16, b2 + (size_t)l * HD,
                                                   h16, nullptr, nullptr);
        else
            k_agg128<true><<<(NN + 7) / 8, 256>>>(g16, b2 + (size_t)l * HD,
                                                  nullptr, W3, tbuf);
    }

    // output: F=1 gather + b3
    k_final<<<(NN + 255) / 256, 256>>>(tbuf, b3, out);
}

// round 14
// speedup vs baseline: 1.0776x; 1.0248x over previous
#include <cuda_runtime.h>
#include <cuda_fp16.h>
#include <cstdint>

#define NN 100000
#define EE 1600000
#define HD 128
#define FIN 64
#define NLAYER 3
#define SCAN_BLK 1024
#define NSCAN ((NN + SCAN_BLK - 1) / SCAN_BLK)   // 98
#define NWELEM (FIN * HD + NLAYER * HD * HD)     // 57344
#define ASTRIDE 40                               // A-stage stride (halves)
#define XQUAD (NN * FIN / 4)                     // 1.6M float4 elements

// ---------------- device scratch ----------------
__device__ float  g_dinv[NN];
__device__ int    g_cnt[NN + 1];           // [NN] = scan done-counter
__device__ int    g_rowptr[NN + 1];
__device__ int    g_blocksum[NSCAN + 1];
__device__ int    g_rank[EE];
__device__ int    g_csr[EE];               // src only (normalization is row-separable)
__device__ float  g_t[NN];                 // holds t-hat = dinv * t
__device__ __half g_x16[(size_t)NN * FIN];
__device__ __half g_a64[(size_t)NN * FIN];
__device__ __half g_h16[(size_t)NN * HD];
__device__ __half g_g16[(size_t)NN * HD];
__device__ __half g_WhiT[NWELEM];          // [n][k] fp16 hi
__device__ __half g_WloT[NWELEM];          // [n][k] fp16 lo

__device__ __forceinline__ uint32_t smem_u32(const void* p) {
    uint32_t a;
    asm("{ .reg .u64 t; cvta.to.shared.u64 t, %1; cvt.u32.u64 %0, t; }" : "=r"(a) : "l"(p));
    return a;
}

// ---------------- prep: weight split + x convert ----------------
__global__ void k_prep(const float* __restrict__ x, const float* __restrict__ W1,
                       const float* __restrict__ W2) {
    int i = blockIdx.x * blockDim.x + threadIdx.x;
    if (i < XQUAD) {
        float4 v = ((const float4*)x)[i];
        __half2 h0 = __floats2half2_rn(v.x, v.y);
        __half2 h1 = __floats2half2_rn(v.z, v.w);
        uint2 o;
        o.x = *reinterpret_cast<uint32_t*>(&h0);
        o.y = *reinterpret_cast<uint32_t*>(&h1);
        ((uint2*)g_x16)[i] = o;
    }
    if (i < NWELEM) {
        float v;
        int oidx;
        if (i < FIN * HD) {
            int k = i / HD, n = i % HD;
            v = W1[i];
            oidx = n * FIN + k;
        } else {
            int j = i - FIN * HD;
            int l = j / (HD * HD), r = j % (HD * HD);
            int k = r / HD, n = r % HD;
            v = W2[j];
            oidx = FIN * HD + l * HD * HD + n * HD + k;
        }
        __half hi = __float2half_rn(v);
        float lof = v - __half2float(hi);
        g_WhiT[oidx] = hi;
        g_WloT[oidx] = __float2half_rn(lof);
    }
}

// scale x in place: x-hat = dinv[row] * x  (runs after dinv is ready)
__global__ void k_scale_x() {
    int i = blockIdx.x * blockDim.x + threadIdx.x;   // uint2 index (4 halves)
    if (i >= NN * 16) return;
    int row = i >> 4;
    float d = g_dinv[row];
    uint2 v = ((uint2*)g_x16)[i];
    float2 f0 = __half22float2(*reinterpret_cast<__half2*>(&v.x));
    float2 f1 = __half22float2(*reinterpret_cast<__half2*>(&v.y));
    __half2 o0 = __floats2half2_rn(f0.x * d, f0.y * d);
    __half2 o1 = __floats2half2_rn(f1.x * d, f1.y * d);
    uint2 o;
    o.x = *reinterpret_cast<uint32_t*>(&o0);
    o.y = *reinterpret_cast<uint32_t*>(&o1);
    ((uint2*)g_x16)[i] = o;
}

// ---------------- degree / norm / CSR build ----------------
__global__ void k_hist(const int* __restrict__ dst) {
    int t = blockIdx.x * blockDim.x + threadIdx.x;
    int e = t * 4;
    if (e + 3 < EE) {
        int4 d = *(const int4*)(dst + e);
        int4 r;
        r.x = atomicAdd(&g_cnt[d.x], 1);
        r.y = atomicAdd(&g_cnt[d.y], 1);
        r.z = atomicAdd(&g_cnt[d.z], 1);
        r.w = atomicAdd(&g_cnt[d.w], 1);
        *(int4*)(g_rank + e) = r;
    } else {
        for (int k = e; k < EE; k++) g_rank[k] = atomicAdd(&g_cnt[dst[k]], 1);
    }
}
__global__ void k_scan1() {
    __shared__ int sh[SCAN_BLK];
    __shared__ int s_last;
    int i = blockIdx.x * SCAN_BLK + threadIdx.x;
    int v = (i < NN) ? g_cnt[i] : 0;
    if (i < NN) g_dinv[i] = rsqrtf((float)(v + 1));
    sh[threadIdx.x] = v;
    __syncthreads();
    int acc = v;
#pragma unroll
    for (int off = 1; off < SCAN_BLK; off <<= 1) {
        int t = (threadIdx.x >= off) ? sh[threadIdx.x - off] : 0;
        __syncthreads();
        acc += t;
        sh[threadIdx.x] = acc;
        __syncthreads();
    }
    if (i < NN) g_rowptr[i] = acc - v;
    if (threadIdx.x == SCAN_BLK - 1) g_blocksum[blockIdx.x] = acc;
    __threadfence();
    __syncthreads();
    if (threadIdx.x == 0) {
        int d = atomicAdd(&g_cnt[NN], 1);
        s_last = (d == NSCAN - 1);
    }
    __syncthreads();
    if (s_last) {
        int j = threadIdx.x;
        int bv = (j < NSCAN) ? g_blocksum[j] : 0;
        sh[threadIdx.x] = bv;
        __syncthreads();
        int bacc = bv;
#pragma unroll
        for (int off = 1; off < 128; off <<= 1) {
            int tt = (j >= off && j < 128) ? sh[j - off] : 0;
            __syncthreads();
            if (j < 128) { bacc += tt; sh[j] = bacc; }
            __syncthreads();
        }
        if (j < NSCAN) g_blocksum[j] = bacc - bv;
    }
}
__global__ void k_scan3() {
    int i = blockIdx.x * blockDim.x + threadIdx.x;
    if (i < NN) g_rowptr[i] += g_blocksum[i / SCAN_BLK];
    if (i == 0) g_rowptr[NN] = EE;
}
// scatter: src index only, no weights, no atomics
__global__ void k_scatter(const int* __restrict__ src, const int* __restrict__ dst) {
    int t = blockIdx.x * blockDim.x + threadIdx.x;
    int e = t * 4;
    if (e + 3 < EE) {
        int4 s4 = *(const int4*)(src + e);
        int4 d4 = *(const int4*)(dst + e);
        int4 r4 = *(const int4*)(g_rank + e);
#pragma unroll
        for (int k = 0; k < 4; k++) {
            int s = (&s4.x)[k], d = (&d4.x)[k], r = (&r4.x)[k];
            g_csr[g_rowptr[d] + r] = s;
        }
    } else {
        for (int k = e; k < EE; k++)
            g_csr[g_rowptr[dst[k]] + g_rank[k]] = src[k];
    }
}

// ---------------- gather aggregations (warp per node), weight-free ----------------
// out = dinv[d] * (sum_{s in N(d)} in[s] + in[d]);  inputs are pre-scaled rows.
__global__ void __launch_bounds__(256)
k_agg64(const __half* __restrict__ in, __half* __restrict__ out) {
    int node = blockIdx.x * 8 + (threadIdx.x >> 5);
    int lane = threadIdx.x & 31;
    if (node >= NN) return;
    const uint32_t* in1 = (const uint32_t*)in;
    uint32_t sv = in1[(size_t)node * 32 + lane];
    float2 f = __half22float2(*reinterpret_cast<__half2*>(&sv));
    float a0 = f.x, a1 = f.y;
    int j = g_rowptr[node], end = g_rowptr[node + 1];
    for (; j + 1 < end; j += 2) {
        int s0 = g_csr[j], s1 = g_csr[j + 1];
        uint32_t v0 = in1[(size_t)s0 * 32 + lane];
        uint32_t v1 = in1[(size_t)s1 * 32 + lane];
        float2 u0 = __half22float2(*reinterpret_cast<__half2*>(&v0));
        float2 u1 = __half22float2(*reinterpret_cast<__half2*>(&v1));
        a0 += u0.x + u1.x;
        a1 += u0.y + u1.y;
    }
    if (j < end) {
        uint32_t v0 = in1[(size_t)g_csr[j] * 32 + lane];
        float2 u0 = __half22float2(*reinterpret_cast<__half2*>(&v0));
        a0 += u0.x; a1 += u0.y;
    }
    float d = g_dinv[node];
    __half2 o = __floats2half2_rn(a0 * d, a1 * d);
    ((uint32_t*)out)[(size_t)node * 32 + lane] = *reinterpret_cast<uint32_t*>(&o);
}

// F=128; out = relu(dinv[d]*sum + bias); LAST also fuses 128->1 matvec, writes t-hat
template <bool LAST>
__global__ void __launch_bounds__(256)
k_agg128(const __half* __restrict__ in, const float* __restrict__ bias,
         __half* __restrict__ out, const float* __restrict__ W3,
         float* __restrict__ tout) {
    int node = blockIdx.x * 8 + (threadIdx.x >> 5);
    int lane = threadIdx.x & 31;
    if (node >= NN) return;
    const uint2* in2 = (const uint2*)in;
    uint2 sv = in2[(size_t)node * 32 + lane];
    float2 f0 = __half22float2(*reinterpret_cast<__half2*>(&sv.x));
    float2 f1 = __half22float2(*reinterpret_cast<__half2*>(&sv.y));
    float a0 = f0.x, a1 = f0.y, a2 = f1.x, a3 = f1.y;

    int j = g_rowptr[node], end = g_rowptr[node + 1];
    for (; j + 1 < end; j += 2) {
        int s0 = g_csr[j], s1 = g_csr[j + 1];
        uint2 v0 = in2[(size_t)s0 * 32 + lane];
        uint2 v1 = in2[(size_t)s1 * 32 + lane];
        float2 u0 = __half22float2(*reinterpret_cast<__half2*>(&v0.x));
        float2 u1 = __half22float2(*reinterpret_cast<__half2*>(&v0.y));
        float2 u2 = __half22float2(*reinterpret_cast<__half2*>(&v1.x));
        float2 u3 = __half22float2(*reinterpret_cast<__half2*>(&v1.y));
        a0 += u0.x + u2.x;
        a1 += u0.y + u2.y;
        a2 += u1.x + u3.x;
        a3 += u1.y + u3.y;
    }
    if (j < end) {
        uint2 v0 = in2[(size_t)g_csr[j] * 32 + lane];
        float2 u0 = __half22float2(*reinterpret_cast<__half2*>(&v0.x));
        float2 u1 = __half22float2(*reinterpret_cast<__half2*>(&v0.y));
        a0 += u0.x; a1 += u0.y; a2 += u1.x; a3 += u1.y;
    }
    float d = g_dinv[node];
    float4 b = *(const float4*)(bias + lane * 4);
    a0 = fmaxf(a0 * d + b.x, 0.f); a1 = fmaxf(a1 * d + b.y, 0.f);
    a2 = fmaxf(a2 * d + b.z, 0.f); a3 = fmaxf(a3 * d + b.w, 0.f);
    if (LAST) {
        float4 w3 = *(const float4*)(W3 + lane * 4);
        float s = a0 * w3.x + a1 * w3.y + a2 * w3.z + a3 * w3.w;
#pragma unroll
        for (int off = 16; off > 0; off >>= 1) s += __shfl_xor_sync(0xffffffffu, s, off);
        if (lane == 0) tout[node] = s * d;   // t-hat = dinv * t
    } else {
        __half2 o0 = __floats2half2_rn(a0, a1);
        __half2 o1 = __floats2half2_rn(a2, a3);
        uint2 ov;
        ov.x = *reinterpret_cast<uint32_t*>(&o0);
        ov.y = *reinterpret_cast<uint32_t*>(&o1);
        ((uint2*)out)[(size_t)node * 32 + lane] = ov;
    }
}

// ---------------- pipelined fp16 GEMM ----------------
// SCALEOUT: multiply output rows by dinv (ONLY when output feeds an aggregation).
#define MMA_F16(d, a0, a1, a2, a3, b0, b1)                                  \
    asm volatile("mma.sync.aligned.m16n8k16.row.col.f32.f16.f16.f32 "       \
                 "{%0,%1,%2,%3}, {%4,%5,%6,%7}, {%8,%9}, {%0,%1,%2,%3};"    \
                 : "+f"(d[0]), "+f"(d[1]), "+f"(d[2]), "+f"(d[3])           \
                 : "r"(a0), "r"(a1), "r"(a2), "r"(a3), "r"(b0), "r"(b1))

template <int K, bool BIASRELU, bool SCALEOUT>
__global__ void __launch_bounds__(256, 2)
k_gemm16(const __half* __restrict__ A, const __half* __restrict__ BhiT,
         const __half* __restrict__ BloT, const float* __restrict__ bias,
         __half* __restrict__ Cout) {
    constexpr int BS = K + 8;
    constexpr int NSTAGE = K / 32;
    constexpr int STAGE_H = 128 * ASTRIDE;
    extern __shared__ __half smbuf[];
    __half* Bh  = smbuf;
    __half* Bl  = Bh + 128 * BS;
    __half* Asm = Bl + 128 * BS;
    uint32_t sA0 = smem_u32(Asm);

    int tid = threadIdx.x;
    int wid = tid >> 5, lane = tid & 31;
    int wr = wid >> 1, wc = wid & 1;
    int row0 = blockIdx.x * 128;
    int mrow = wr * 32;
    int ncol = wc * 64;
    int lq = lane >> 2;
    int lr = lane & 3;

    constexpr int BCH = K / 8;
    for (int idx = tid; idx < 128 * BCH; idx += 256) {
        int n = idx / BCH, c = (idx % BCH) * 8;
        *(uint4*)&Bh[n * BS + c] = *(const uint4*)(BhiT + (size_t)n * K + c);
        *(uint4*)&Bl[n * BS + c] = *(const uint4*)(BloT + (size_t)n * K + c);
    }

    auto loadA = [&](int stage, int k0) {
#pragma unroll
        for (int i = 0; i < 2; i++) {
            int li = tid + i * 256;
            int r = li >> 2;
            int c = (li & 3) * 8;
            int gr = row0 + r;
            const void* src = (gr < NN) ? (const void*)(A + (size_t)gr * K + k0 + c)
                                        : (const void*)A;
            int sz = (gr < NN) ? 16 : 0;
            uint32_t d = sA0 + (stage * STAGE_H + r * ASTRIDE + c) * 2;
            asm volatile("cp.async.ca.shared.global [%0], [%1], 16, %2;"
                         :: "r"(d), "l"(src), "r"(sz));
        }
        asm volatile("cp.async.commit_group;" ::: "memory");
    };

    float acc[2][8][4];
#pragma unroll
    for (int ma = 0; ma < 2; ma++)
#pragma unroll
        for (int na = 0; na < 8; na++)
#pragma unroll
            for (int r = 0; r < 4; r++) acc[ma][na][r] = 0.0f;

    loadA(0, 0);

#pragma unroll
    for (int st = 0; st < NSTAGE; st++) {
        if (st + 1 < NSTAGE) loadA((st + 1) & 1, (st + 1) * 32);
        if (st + 1 < NSTAGE)
            asm volatile("cp.async.wait_group 1;" ::: "memory");
        else
            asm volatile("cp.async.wait_group 0;" ::: "memory");
        __syncthreads();

        const __half* Ast = Asm + (st & 1) * STAGE_H;
        int gk0 = st * 32;
#pragma unroll
        for (int ks = 0; ks < 2; ks++) {
            int kk = ks * 16;
            int gk = gk0 + kk;
            uint32_t a[2][4];
#pragma unroll
            for (int ma = 0; ma < 2; ma++) {
                int rb = mrow + ma * 16;
                a[ma][0] = *(const uint32_t*)&Ast[(rb + lq) * ASTRIDE + kk + 2 * lr];
                a[ma][1] = *(const uint32_t*)&Ast[(rb + lq + 8) * ASTRIDE + kk + 2 * lr];
                a[ma][2] = *(const uint32_t*)&Ast[(rb + lq) * ASTRIDE + kk + 2 * lr + 8];
                a[ma][3] = *(const uint32_t*)&Ast[(rb + lq + 8) * ASTRIDE + kk + 2 * lr + 8];
            }
#pragma unroll
            for (int na = 0; na < 8; na++) {
                int n = ncol + na * 8 + lq;
                uint32_t bh0 = *(const uint32_t*)&Bh[n * BS + gk + 2 * lr];
                uint32_t bh1 = *(const uint32_t*)&Bh[n * BS + gk + 2 * lr + 8];
                uint32_t bl0 = *(const uint32_t*)&Bl[n * BS + gk + 2 * lr];
                uint32_t bl1 = *(const uint32_t*)&Bl[n * BS + gk + 2 * lr + 8];
#pragma unroll
                for (int ma = 0; ma < 2; ma++) {
                    MMA_F16(acc[ma][na], a[ma][0], a[ma][1], a[ma][2], a[ma][3], bh0, bh1);
                    MMA_F16(acc[ma][na], a[ma][0], a[ma][1], a[ma][2], a[ma][3], bl0, bl1);
                }
            }
        }
        __syncthreads();
    }

#pragma unroll
    for (int ma = 0; ma < 2; ma++) {
        int r0 = row0 + mrow + ma * 16 + lq;
        float d0 = 1.f, d1 = 1.f;
        if (SCALEOUT) {
            d0 = (r0 < NN) ? g_dinv[r0] : 0.f;
            d1 = (r0 + 8 < NN) ? g_dinv[r0 + 8] : 0.f;
        }
#pragma unroll
        for (int na = 0; na < 8; na++) {
            int col = ncol + na * 8 + 2 * lr;
            float c0 = acc[ma][na][0], c1 = acc[ma][na][1];
            float c2 = acc[ma][na][2], c3 = acc[ma][na][3];
            if (BIASRELU) {
                float bx = bias[col], by = bias[col + 1];
                c0 = fmaxf(c0 + bx, 0.f); c1 = fmaxf(c1 + by, 0.f);
                c2 = fmaxf(c2 + bx, 0.f); c3 = fmaxf(c3 + by, 0.f);
            }
            if (SCALEOUT) { c0 *= d0; c1 *= d0; c2 *= d1; c3 *= d1; }
            if (r0 < NN)     *(__half2*)(Cout + (size_t)r0 * 128 + col) = __floats2half2_rn(c0, c1);
            if (r0 + 8 < NN) *(__half2*)(Cout + (size_t)(r0 + 8) * 128 + col) = __floats2half2_rn(c2, c3);
        }
    }
}

// ---------------- output: F=1 gather (weight-free) ----------------
__global__ void k_final(const float* __restrict__ t, const float* __restrict__ b3,
                        float* __restrict__ out) {
    int i = blockIdx.x * blockDim.x + threadIdx.x;
    if (i >= NN) return;
    float s = t[i];                           // t-hat self term
    int j = g_rowptr[i], end = g_rowptr[i + 1];
    for (; j < end; j++) s += t[g_csr[j]];
    out[i] = g_dinv[i] * s + b3[0];
}

// ---------------- launch ----------------
extern "C" void kernel_launch(void* const* d_in, const int* in_sizes, int n_in,
                              void* d_out, int out_size) {
    const float* x  = (const float*)d_in[0];
    const int* ei   = (const int*)d_in[1];
    const float* W1 = (const float*)d_in[2];
    const float* b1 = (const float*)d_in[3];
    const float* W2 = (const float*)d_in[4];
    const float* b2 = (const float*)d_in[5];
    const float* W3 = (const float*)d_in[6];
    const float* b3 = (const float*)d_in[7];
    float* out = (float*)d_out;

    const int* src = ei;
    const int* dst = ei + EE;

    __half* x16;  cudaGetSymbolAddress((void**)&x16, g_x16);
    __half* a64;  cudaGetSymbolAddress((void**)&a64, g_a64);
    __half* h16;  cudaGetSymbolAddress((void**)&h16, g_h16);
    __half* g16;  cudaGetSymbolAddress((void**)&g16, g_g16);
    __half* whiT; cudaGetSymbolAddress((void**)&whiT, g_WhiT);
    __half* wloT; cudaGetSymbolAddress((void**)&wloT, g_WloT);
    float* tbuf;  cudaGetSymbolAddress((void**)&tbuf, g_t);
    int* cntp;    cudaGetSymbolAddress((void**)&cntp, g_cnt);

    constexpr int SM64  = (2 * 128 * (FIN + 8) + 2 * 128 * ASTRIDE) * 2;  // 57344
    constexpr int SM128 = (2 * 128 * (HD + 8) + 2 * 128 * ASTRIDE) * 2;   // 90112

    static cudaStream_t s2 = nullptr;
    static cudaEvent_t evFork = nullptr, evDinv = nullptr, evJoin = nullptr;
    if (!s2) {
        cudaStreamCreateWithFlags(&s2, cudaStreamNonBlocking);
        cudaEventCreateWithFlags(&evFork, cudaEventDisableTiming);
        cudaEventCreateWithFlags(&evDinv, cudaEventDisableTiming);
        cudaEventCreateWithFlags(&evJoin, cudaEventDisableTiming);
        cudaFuncSetAttribute(k_gemm16<FIN, true, false>,
                             cudaFuncAttributeMaxDynamicSharedMemorySize, SM64);
        cudaFuncSetAttribute(k_gemm16<HD, false, true>,
                             cudaFuncAttributeMaxDynamicSharedMemorySize, SM128);
    }

    // fork: CSR chain on s2, prep on main stream
    cudaEventRecord(evFork, 0);
    cudaStreamWaitEvent(s2, evFork, 0);

    cudaMemsetAsync(cntp, 0, (NN + 1) * sizeof(int), s2);
    k_hist<<<(EE / 4 + 255) / 256, 256, 0, s2>>>(dst);
    k_scan1<<<NSCAN, SCAN_BLK, 0, s2>>>();
    cudaEventRecord(evDinv, s2);              // dinv ready
    k_scan3<<<(NN + 255) / 256, 256, 0, s2>>>();
    k_scatter<<<(EE / 4 + 255) / 256, 256, 0, s2>>>(src, dst);
    cudaEventRecord(evJoin, s2);

    k_prep<<<(XQUAD + 255) / 256, 256>>>(x, W1, W2);
    // scale x by dinv on main (hidden under scan3+scatter on s2)
    cudaStreamWaitEvent(0, evDinv, 0);
    k_scale_x<<<(NN * 16 + 255) / 256, 256>>>();

    // join: CSR needed from here on
    cudaStreamWaitEvent(0, evJoin, 0);

    const int GB = (NN + 127) / 128;

    // layer 1: weight-free agg at F=64, then GEMM (bias+relu, NO output scaling —
    // its output feeds the next GEMM, not an aggregation)
    k_agg64<<<(NN + 7) / 8, 256>>>(x16, a64);
    k_gemm16<FIN, true, false><<<GB, 256, SM64>>>(a64, whiT, wloT, b1, h16);

    // hidden layers: GEMM (row-scaled out, feeds agg) then agg (bias+relu)
    for (int l = 0; l < NLAYER; l++) {
        const __half* bh = whiT + FIN * HD + (size_t)l * HD * HD;
        const __half* bl = wloT + FIN * HD + (size_t)l * HD * HD;
        k_gemm16<HD, false, true><<<GB, 256, SM128>>>(h16, bh, bl, nullptr, g16);
        if (l < NLAYER - 1)
            k_agg128<false><<<(NN + 7) / 8, 256>>>(g16, b2 + (size_t)l * HD,
                                                   h16, nullptr, nullptr);
        else
            k_agg128<true><<<(NN + 7) / 8, 256>>>(g16, b2 + (size_t)l * HD,
                                                  nullptr, W3, tbuf);
    }

    // output: F=1 gather + b3
    k_final<<<(NN + 255) / 256, 256>>>(tbuf, b3, out);
}

// round 15
// speedup vs baseline: 1.1073x; 1.0275x over previous
#include <cuda_runtime.h>
#include <cuda_fp16.h>
#include <cstdint>

#define NN 100000
#define EE 1600000
#define HD 128
#define FIN 64
#define NLAYER 3
#define SCAN_BLK 1024
#define NSCAN ((NN + SCAN_BLK - 1) / SCAN_BLK)   // 98
#define NWELEM (FIN * HD + NLAYER * HD * HD)     // 57344
#define ASTRIDE 40                               // A-stage stride (halves)
#define XQUAD (NN * FIN / 4)                     // 1.6M float4 elements
// packed-B sizes (uint4 units): layer1 = (64/16)*128*4, hidden = (128/16)*128*4
#define PK1 2048
#define PKH 4096
#define PKTOT (PK1 + NLAYER * PKH)               // 14336 uint4

// ---------------- device scratch ----------------
__device__ float  g_dinv[NN];
__device__ int    g_cnt[NN + 1];           // [NN] = scan done-counter
__device__ int    g_rowptr[NN + 1];
__device__ int    g_blocksum[NSCAN + 1];
__device__ int    g_rank[EE];
__device__ int    g_csr[EE];               // src only (normalization is row-separable)
__device__ float  g_t[NN];                 // t-hat = dinv * t
__device__ __half g_x16[(size_t)NN * FIN];
__device__ __half g_a64[(size_t)NN * FIN];
__device__ __half g_h16[(size_t)NN * HD];
__device__ __half g_g16[(size_t)NN * HD];
__device__ uint4  g_Wpk[PKTOT];            // fragment-packed weights {bh0,bh1,bl0,bl1}

__device__ __forceinline__ uint32_t smem_u32(const void* p) {
    uint32_t a;
    asm("{ .reg .u64 t; cvta.to.shared.u64 t, %1; cvt.u32.u64 %0, t; }" : "=r"(a) : "l"(p));
    return a;
}

// ---------------- prep: weight split+pack + x convert ----------------
__global__ void k_prep(const float* __restrict__ x, const float* __restrict__ W1,
                       const float* __restrict__ W2) {
    int i = blockIdx.x * blockDim.x + threadIdx.x;
    if (i < XQUAD) {
        float4 v = ((const float4*)x)[i];
        __half2 h0 = __floats2half2_rn(v.x, v.y);
        __half2 h1 = __floats2half2_rn(v.z, v.w);
        uint2 o;
        o.x = *reinterpret_cast<uint32_t*>(&h0);
        o.y = *reinterpret_cast<uint32_t*>(&h1);
        ((uint2*)g_x16)[i] = o;
    }
    if (i < NWELEM) {
        float v;
        int k, n, ebase;
        if (i < FIN * HD) {                  // W1[k][n]
            k = i / HD; n = i % HD;
            v = W1[i];
            ebase = 0;
        } else {
            int j = i - FIN * HD;
            int l = j / (HD * HD), r = j % (HD * HD);
            k = r / HD; n = r % HD;
            v = W2[j];
            ebase = PK1 + l * PKH;
        }
        __half hi = __float2half_rn(v);
        float lof = v - __half2float(hi);
        __half lo = __float2half_rn(lof);
        int kc = k >> 4, rem = k & 15;
        int lr = (rem & 7) >> 1, part = rem >> 3, hp = rem & 1;
        int e = ebase + (kc * 128 + n) * 4 + lr;
        __half* base = (__half*)&g_Wpk[e];
        base[part * 2 + hp] = hi;            // words 0,1 = bh0,bh1
        base[4 + part * 2 + hp] = lo;        // words 2,3 = bl0,bl1
    }
}

// scale x in place: x-hat = dinv[row] * x
__global__ void k_scale_x() {
    int i = blockIdx.x * blockDim.x + threadIdx.x;   // uint2 index (4 halves)
    if (i >= NN * 16) return;
    int row = i >> 4;
    float d = g_dinv[row];
    uint2 v = ((uint2*)g_x16)[i];
    float2 f0 = __half22float2(*reinterpret_cast<__half2*>(&v.x));
    float2 f1 = __half22float2(*reinterpret_cast<__half2*>(&v.y));
    __half2 o0 = __floats2half2_rn(f0.x * d, f0.y * d);
    __half2 o1 = __floats2half2_rn(f1.x * d, f1.y * d);
    uint2 o;
    o.x = *reinterpret_cast<uint32_t*>(&o0);
    o.y = *reinterpret_cast<uint32_t*>(&o1);
    ((uint2*)g_x16)[i] = o;
}

// ---------------- degree / norm / CSR build ----------------
__global__ void k_hist(const int* __restrict__ dst) {
    int t = blockIdx.x * blockDim.x + threadIdx.x;
    int e = t * 8;
    if (e + 7 < EE) {
        int4 d0 = *(const int4*)(dst + e);
        int4 d1 = *(const int4*)(dst + e + 4);
        int4 r0, r1;
        r0.x = atomicAdd(&g_cnt[d0.x], 1);
        r0.y = atomicAdd(&g_cnt[d0.y], 1);
        r0.z = atomicAdd(&g_cnt[d0.z], 1);
        r0.w = atomicAdd(&g_cnt[d0.w], 1);
        r1.x = atomicAdd(&g_cnt[d1.x], 1);
        r1.y = atomicAdd(&g_cnt[d1.y], 1);
        r1.z = atomicAdd(&g_cnt[d1.z], 1);
        r1.w = atomicAdd(&g_cnt[d1.w], 1);
        *(int4*)(g_rank + e) = r0;
        *(int4*)(g_rank + e + 4) = r1;
    } else {
        for (int k = e; k < EE; k++) g_rank[k] = atomicAdd(&g_cnt[dst[k]], 1);
    }
}
__global__ void k_scan1() {
    __shared__ int sh[SCAN_BLK];
    __shared__ int s_last;
    int i = blockIdx.x * SCAN_BLK + threadIdx.x;
    int v = (i < NN) ? g_cnt[i] : 0;
    if (i < NN) g_dinv[i] = rsqrtf((float)(v + 1));
    sh[threadIdx.x] = v;
    __syncthreads();
    int acc = v;
#pragma unroll
    for (int off = 1; off < SCAN_BLK; off <<= 1) {
        int t = (threadIdx.x >= off) ? sh[threadIdx.x - off] : 0;
        __syncthreads();
        acc += t;
        sh[threadIdx.x] = acc;
        __syncthreads();
    }
    if (i < NN) g_rowptr[i] = acc - v;
    if (threadIdx.x == SCAN_BLK - 1) g_blocksum[blockIdx.x] = acc;
    __threadfence();
    __syncthreads();
    if (threadIdx.x == 0) {
        int d = atomicAdd(&g_cnt[NN], 1);
        s_last = (d == NSCAN - 1);
    }
    __syncthreads();
    if (s_last) {
        int j = threadIdx.x;
        int bv = (j < NSCAN) ? g_blocksum[j] : 0;
        sh[threadIdx.x] = bv;
        __syncthreads();
        int bacc = bv;
#pragma unroll
        for (int off = 1; off < 128; off <<= 1) {
            int tt = (j >= off && j < 128) ? sh[j - off] : 0;
            __syncthreads();
            if (j < 128) { bacc += tt; sh[j] = bacc; }
            __syncthreads();
        }
        if (j < NSCAN) g_blocksum[j] = bacc - bv;
    }
}
__global__ void k_scan3() {
    int i = blockIdx.x * blockDim.x + threadIdx.x;
    if (i < NN) g_rowptr[i] += g_blocksum[i / SCAN_BLK];
    if (i == 0) g_rowptr[NN] = EE;
}
__global__ void k_scatter(const int* __restrict__ src, const int* __restrict__ dst) {
    int t = blockIdx.x * blockDim.x + threadIdx.x;
    int e = t * 8;
    if (e + 7 < EE) {
        int4 s0 = *(const int4*)(src + e);
        int4 s1 = *(const int4*)(src + e + 4);
        int4 d0 = *(const int4*)(dst + e);
        int4 d1 = *(const int4*)(dst + e + 4);
        int4 r0 = *(const int4*)(g_rank + e);
        int4 r1 = *(const int4*)(g_rank + e + 4);
        g_csr[g_rowptr[d0.x] + r0.x] = s0.x;
        g_csr[g_rowptr[d0.y] + r0.y] = s0.y;
        g_csr[g_rowptr[d0.z] + r0.z] = s0.z;
        g_csr[g_rowptr[d0.w] + r0.w] = s0.w;
        g_csr[g_rowptr[d1.x] + r1.x] = s1.x;
        g_csr[g_rowptr[d1.y] + r1.y] = s1.y;
        g_csr[g_rowptr[d1.z] + r1.z] = s1.z;
        g_csr[g_rowptr[d1.w] + r1.w] = s1.w;
    } else {
        for (int k = e; k < EE; k++)
            g_csr[g_rowptr[dst[k]] + g_rank[k]] = src[k];
    }
}

// ---------------- gather aggregations (warp per node), weight-free ----------------
__global__ void __launch_bounds__(256)
k_agg64(const __half* __restrict__ in, __half* __restrict__ out) {
    int node = blockIdx.x * 8 + (threadIdx.x >> 5);
    int lane = threadIdx.x & 31;
    if (node >= NN) return;
    const uint32_t* in1 = (const uint32_t*)in;
    uint32_t sv = in1[(size_t)node * 32 + lane];
    float2 f = __half22float2(*reinterpret_cast<__half2*>(&sv));
    float a0 = f.x, a1 = f.y;
    int j = g_rowptr[node], end = g_rowptr[node + 1];
    for (; j + 3 < end; j += 4) {
        int s0 = g_csr[j], s1 = g_csr[j + 1], s2 = g_csr[j + 2], s3 = g_csr[j + 3];
        uint32_t v0 = in1[(size_t)s0 * 32 + lane];
        uint32_t v1 = in1[(size_t)s1 * 32 + lane];
        uint32_t v2 = in1[(size_t)s2 * 32 + lane];
        uint32_t v3 = in1[(size_t)s3 * 32 + lane];
        float2 u0 = __half22float2(*reinterpret_cast<__half2*>(&v0));
        float2 u1 = __half22float2(*reinterpret_cast<__half2*>(&v1));
        float2 u2 = __half22float2(*reinterpret_cast<__half2*>(&v2));
        float2 u3 = __half22float2(*reinterpret_cast<__half2*>(&v3));
        a0 += (u0.x + u1.x) + (u2.x + u3.x);
        a1 += (u0.y + u1.y) + (u2.y + u3.y);
    }
    for (; j < end; j++) {
        uint32_t v0 = in1[(size_t)g_csr[j] * 32 + lane];
        float2 u0 = __half22float2(*reinterpret_cast<__half2*>(&v0));
        a0 += u0.x; a1 += u0.y;
    }
    float d = g_dinv[node];
    __half2 o = __floats2half2_rn(a0 * d, a1 * d);
    ((uint32_t*)out)[(size_t)node * 32 + lane] = *reinterpret_cast<uint32_t*>(&o);
}

template <bool LAST>
__global__ void __launch_bounds__(256)
k_agg128(const __half* __restrict__ in, const float* __restrict__ bias,
         __half* __restrict__ out, const float* __restrict__ W3,
         float* __restrict__ tout) {
    int node = blockIdx.x * 8 + (threadIdx.x >> 5);
    int lane = threadIdx.x & 31;
    if (node >= NN) return;
    const uint2* in2 = (const uint2*)in;
    uint2 sv = in2[(size_t)node * 32 + lane];
    float2 f0 = __half22float2(*reinterpret_cast<__half2*>(&sv.x));
    float2 f1 = __half22float2(*reinterpret_cast<__half2*>(&sv.y));
    float a0 = f0.x, a1 = f0.y, a2 = f1.x, a3 = f1.y;

    int j = g_rowptr[node], end = g_rowptr[node + 1];
    for (; j + 3 < end; j += 4) {
        int s0 = g_csr[j], s1 = g_csr[j + 1], s2 = g_csr[j + 2], s3 = g_csr[j + 3];
        uint2 v0 = in2[(size_t)s0 * 32 + lane];
        uint2 v1 = in2[(size_t)s1 * 32 + lane];
        uint2 v2 = in2[(size_t)s2 * 32 + lane];
        uint2 v3 = in2[(size_t)s3 * 32 + lane];
        float2 u0 = __half22float2(*reinterpret_cast<__half2*>(&v0.x));
        float2 u1 = __half22float2(*reinterpret_cast<__half2*>(&v0.y));
        float2 u2 = __half22float2(*reinterpret_cast<__half2*>(&v1.x));
        float2 u3 = __half22float2(*reinterpret_cast<__half2*>(&v1.y));
        float2 u4 = __half22float2(*reinterpret_cast<__half2*>(&v2.x));
        float2 u5 = __half22float2(*reinterpret_cast<__half2*>(&v2.y));
        float2 u6 = __half22float2(*reinterpret_cast<__half2*>(&v3.x));
        float2 u7 = __half22float2(*reinterpret_cast<__half2*>(&v3.y));
        a0 += (u0.x + u2.x) + (u4.x + u6.x);
        a1 += (u0.y + u2.y) + (u4.y + u6.y);
        a2 += (u1.x + u3.x) + (u5.x + u7.x);
        a3 += (u1.y + u3.y) + (u5.y + u7.y);
    }
    for (; j < end; j++) {
        uint2 v0 = in2[(size_t)g_csr[j] * 32 + lane];
        float2 u0 = __half22float2(*reinterpret_cast<__half2*>(&v0.x));
        float2 u1 = __half22float2(*reinterpret_cast<__half2*>(&v0.y));
        a0 += u0.x; a1 += u0.y; a2 += u1.x; a3 += u1.y;
    }
    float d = g_dinv[node];
    float4 b = *(const float4*)(bias + lane * 4);
    a0 = fmaxf(a0 * d + b.x, 0.f); a1 = fmaxf(a1 * d + b.y, 0.f);
    a2 = fmaxf(a2 * d + b.z, 0.f); a3 = fmaxf(a3 * d + b.w, 0.f);
    if (LAST) {
        float4 w3 = *(const float4*)(W3 + lane * 4);
        float s = a0 * w3.x + a1 * w3.y + a2 * w3.z + a3 * w3.w;
#pragma unroll
        for (int off = 16; off > 0; off >>= 1) s += __shfl_xor_sync(0xffffffffu, s, off);
        if (lane == 0) tout[node] = s * d;   // t-hat
    } else {
        __half2 o0 = __floats2half2_rn(a0, a1);
        __half2 o1 = __floats2half2_rn(a2, a3);
        uint2 ov;
        ov.x = *reinterpret_cast<uint32_t*>(&o0);
        ov.y = *reinterpret_cast<uint32_t*>(&o1);
        ((uint2*)out)[(size_t)node * 32 + lane] = ov;
    }
}

// ---------------- pipelined fp16 GEMM with fragment-packed B ----------------
#define MMA_F16(d, a0, a1, a2, a3, b0, b1)                                  \
    asm volatile("mma.sync.aligned.m16n8k16.row.col.f32.f16.f16.f32 "       \
                 "{%0,%1,%2,%3}, {%4,%5,%6,%7}, {%8,%9}, {%0,%1,%2,%3};"    \
                 : "+f"(d[0]), "+f"(d[1]), "+f"(d[2]), "+f"(d[3])           \
                 : "r"(a0), "r"(a1), "r"(a2), "r"(a3), "r"(b0), "r"(b1))

template <int K, bool BIASRELU, bool SCALEOUT>
__global__ void __launch_bounds__(256, 2)
k_gemm16(const __half* __restrict__ A, const uint4* __restrict__ Wpk,
         const float* __restrict__ bias, __half* __restrict__ Cout) {
    constexpr int NPK = (K / 16) * 512;      // packed-B uint4 count
    constexpr int NSTAGE = K / 32;
    constexpr int STAGE_H = 128 * ASTRIDE;
    extern __shared__ __align__(16) char smraw[];
    uint4* Bp  = (uint4*)smraw;              // NPK uint4
    __half* Asm = (__half*)(smraw + NPK * 16);
    uint32_t sA0 = smem_u32(Asm);

    int tid = threadIdx.x;
    int wid = tid >> 5, lane = tid & 31;
    int wr = wid >> 1, wc = wid & 1;
    int row0 = blockIdx.x * 128;
    int mrow = wr * 32;
    int ncol = wc * 64;
    int lq = lane >> 2;
    int lr = lane & 3;

    // stage packed B (linear copy)
    for (int idx = tid; idx < NPK; idx += 256) Bp[idx] = Wpk[idx];

    auto loadA = [&](int stage, int k0) {
#pragma unroll
        for (int i = 0; i < 2; i++) {
            int li = tid + i * 256;
            int r = li >> 2;
            int c = (li & 3) * 8;
            int gr = row0 + r;
            const void* src = (gr < NN) ? (const void*)(A + (size_t)gr * K + k0 + c)
                                        : (const void*)A;
            int sz = (gr < NN) ? 16 : 0;
            uint32_t d = sA0 + (stage * STAGE_H + r * ASTRIDE + c) * 2;
            asm volatile("cp.async.ca.shared.global [%0], [%1], 16, %2;"
                         :: "r"(d), "l"(src), "r"(sz));
        }
        asm volatile("cp.async.commit_group;" ::: "memory");
    };

    float acc[2][8][4];
#pragma unroll
    for (int ma = 0; ma < 2; ma++)
#pragma unroll
        for (int na = 0; na < 8; na++)
#pragma unroll
            for (int r = 0; r < 4; r++) acc[ma][na][r] = 0.0f;

    loadA(0, 0);

#pragma unroll
    for (int st = 0; st < NSTAGE; st++) {
        if (st + 1 < NSTAGE) loadA((st + 1) & 1, (st + 1) * 32);
        if (st + 1 < NSTAGE)
            asm volatile("cp.async.wait_group 1;" ::: "memory");
        else
            asm volatile("cp.async.wait_group 0;" ::: "memory");
        __syncthreads();

        const __half* Ast = Asm + (st & 1) * STAGE_H;
#pragma unroll
        for (int ks = 0; ks < 2; ks++) {
            int kk = ks * 16;
            int kc = st * 2 + ks;
            uint32_t a[2][4];
#pragma unroll
            for (int ma = 0; ma < 2; ma++) {
                int rb = mrow + ma * 16;
                a[ma][0] = *(const uint32_t*)&Ast[(rb + lq) * ASTRIDE + kk + 2 * lr];
                a[ma][1] = *(const uint32_t*)&Ast[(rb + lq + 8) * ASTRIDE + kk + 2 * lr];
                a[ma][2] = *(const uint32_t*)&Ast[(rb + lq) * ASTRIDE + kk + 2 * lr + 8];
                a[ma][3] = *(const uint32_t*)&Ast[(rb + lq + 8) * ASTRIDE + kk + 2 * lr + 8];
            }
            int ebase = kc * 512 + (ncol + lq) * 4 + lr;
#pragma unroll
            for (int na = 0; na < 8; na++) {
                uint4 b = Bp[ebase + na * 32];   // {bh0, bh1, bl0, bl1}
#pragma unroll
                for (int ma = 0; ma < 2; ma++) {
                    MMA_F16(acc[ma][na], a[ma][0], a[ma][1], a[ma][2], a[ma][3], b.x, b.y);
                    MMA_F16(acc[ma][na], a[ma][0], a[ma][1], a[ma][2], a[ma][3], b.z, b.w);
                }
            }
        }
        __syncthreads();
    }

#pragma unroll
    for (int ma = 0; ma < 2; ma++) {
        int r0 = row0 + mrow + ma * 16 + lq;
        float d0 = 1.f, d1 = 1.f;
        if (SCALEOUT) {
            d0 = (r0 < NN) ? g_dinv[r0] : 0.f;
            d1 = (r0 + 8 < NN) ? g_dinv[r0 + 8] : 0.f;
        }
#pragma unroll
        for (int na = 0; na < 8; na++) {
            int col = ncol + na * 8 + 2 * lr;
            float c0 = acc[ma][na][0], c1 = acc[ma][na][1];
            float c2 = acc[ma][na][2], c3 = acc[ma][na][3];
            if (BIASRELU) {
                float bx = bias[col], by = bias[col + 1];
                c0 = fmaxf(c0 + bx, 0.f); c1 = fmaxf(c1 + by, 0.f);
                c2 = fmaxf(c2 + bx, 0.f); c3 = fmaxf(c3 + by, 0.f);
            }
            if (SCALEOUT) { c0 *= d0; c1 *= d0; c2 *= d1; c3 *= d1; }
            if (r0 < NN)     *(__half2*)(Cout + (size_t)r0 * 128 + col) = __floats2half2_rn(c0, c1);
            if (r0 + 8 < NN) *(__half2*)(Cout + (size_t)(r0 + 8) * 128 + col) = __floats2half2_rn(c2, c3);
        }
    }
}

// ---------------- output: F=1 gather (weight-free) ----------------
__global__ void k_final(const float* __restrict__ t, const float* __restrict__ b3,
                        float* __restrict__ out) {
    int i = blockIdx.x * blockDim.x + threadIdx.x;
    if (i >= NN) return;
    float s = t[i];
    int j = g_rowptr[i], end = g_rowptr[i + 1];
    for (; j < end; j++) s += t[g_csr[j]];
    out[i] = g_dinv[i] * s + b3[0];
}

// ---------------- launch ----------------
extern "C" void kernel_launch(void* const* d_in, const int* in_sizes, int n_in,
                              void* d_out, int out_size) {
    const float* x  = (const float*)d_in[0];
    const int* ei   = (const int*)d_in[1];
    const float* W1 = (const float*)d_in[2];
    const float* b1 = (const float*)d_in[3];
    const float* W2 = (const float*)d_in[4];
    const float* b2 = (const float*)d_in[5];
    const float* W3 = (const float*)d_in[6];
    const float* b3 = (const float*)d_in[7];
    float* out = (float*)d_out;

    const int* src = ei;
    const int* dst = ei + EE;

    __half* x16;  cudaGetSymbolAddress((void**)&x16, g_x16);
    __half* a64;  cudaGetSymbolAddress((void**)&a64, g_a64);
    __half* h16;  cudaGetSymbolAddress((void**)&h16, g_h16);
    __half* g16;  cudaGetSymbolAddress((void**)&g16, g_g16);
    uint4* wpk;   cudaGetSymbolAddress((void**)&wpk, g_Wpk);
    float* tbuf;  cudaGetSymbolAddress((void**)&tbuf, g_t);
    int* cntp;    cudaGetSymbolAddress((void**)&cntp, g_cnt);

    constexpr int SM64  = (FIN / 16) * 512 * 16 + 2 * 128 * ASTRIDE * 2;  // 53248
    constexpr int SM128 = (HD / 16) * 512 * 16 + 2 * 128 * ASTRIDE * 2;   // 86016

    static cudaStream_t s2 = nullptr;
    static cudaEvent_t evFork = nullptr, evDinv = nullptr, evJoin = nullptr;
    if (!s2) {
        cudaStreamCreateWithFlags(&s2, cudaStreamNonBlocking);
        cudaEventCreateWithFlags(&evFork, cudaEventDisableTiming);
        cudaEventCreateWithFlags(&evDinv, cudaEventDisableTiming);
        cudaEventCreateWithFlags(&evJoin, cudaEventDisableTiming);
        cudaFuncSetAttribute(k_gemm16<FIN, true, false>,
                             cudaFuncAttributeMaxDynamicSharedMemorySize, SM64);
        cudaFuncSetAttribute(k_gemm16<HD, false, true>,
                             cudaFuncAttributeMaxDynamicSharedMemorySize, SM128);
    }

    // fork: CSR chain on s2, prep on main stream
    cudaEventRecord(evFork, 0);
    cudaStreamWaitEvent(s2, evFork, 0);

    cudaMemsetAsync(cntp, 0, (NN + 1) * sizeof(int), s2);
    k_hist<<<(EE / 8 + 255) / 256, 256, 0, s2>>>(dst);
    k_scan1<<<NSCAN, SCAN_BLK, 0, s2>>>();
    cudaEventRecord(evDinv, s2);
    k_scan3<<<(NN + 255) / 256, 256, 0, s2>>>();
    k_scatter<<<(EE / 8 + 255) / 256, 256, 0, s2>>>(src, dst);
    cudaEventRecord(evJoin, s2);

    k_prep<<<(XQUAD + 255) / 256, 256>>>(x, W1, W2);
    cudaStreamWaitEvent(0, evDinv, 0);
    k_scale_x<<<(NN * 16 + 255) / 256, 256>>>();

    cudaStreamWaitEvent(0, evJoin, 0);

    const int GB = (NN + 127) / 128;

    // layer 1: weight-free agg at F=64, then GEMM (bias+relu, no out-scale)
    k_agg64<<<(NN + 7) / 8, 256>>>(x16, a64);
    k_gemm16<FIN, true, false><<<GB, 256, SM64>>>(a64, wpk, b1, h16);

    // hidden layers: GEMM (row-scaled out) then agg (bias+relu); last fuses matvec
    for (int l = 0; l < NLAYER; l++) {
        const uint4* wl = wpk + PK1 + (size_t)l * PKH;
        k_gemm16<HD, false, true><<<GB, 256, SM128>>>(h16, wl, nullptr, g16);
        if (l < NLAYER - 1)
            k_agg128<false><<<(NN + 7) / 8, 256>>>(g16, b2 + (size_t)l * HD,
                                                   h16, nullptr, nullptr);
        else
            k_agg128<true><<<(NN + 7) / 8, 256>>>(g16, b2 + (size_t)l * HD,
                                                  nullptr, W3, tbuf);
    }

    // output: F=1 gather + b3
    k_final<<<(NN + 255) / 256, 256>>>(tbuf, b3, out);
}